// round 9
// baseline (speedup 1.0000x reference)
#include <cuda_runtime.h>
#include <cuda_fp16.h>
#include <math.h>

// NO __device__ globals, NO static-init CUDA calls, NO local arrays.
// Scratch carved out of d_out (N*20 + N*32 floats = 20.8 MB):
//   [0      , 6.4MB)  X   : fp16 feature staging, N*32 halves (t1 / h1 / t2, reused)
//   [6.4MB  , 6.8MB)  dis : fp32 N      (1/sqrt(deg))
//   [6.8MB  , 7.2MB)  deg : int  N
//   [8.0MB  , 20.8MB) Y   : fp32 N*32   (atomic accumulator; finally holds h2 = output)
// INVARIANT: dis/deg/X are read ONLY by kernels that run before cls_fused;
// cls_fused (which writes out[0,8MB)) reads only Y + harness inputs.
// dis[dst] scaling is folded into the aggregation pushes for this reason.

#define HID 32

// ---------------- degree ----------------
__global__ __launch_bounds__(256) void count_deg_kernel(const int* __restrict__ col,
                                                        int* __restrict__ deg, int e) {
    int i = blockIdx.x * blockDim.x + threadIdx.x;
    if (i < e) atomicAdd(&deg[col[i]], 1);
}

__global__ __launch_bounds__(256) void make_dis_kernel(const int* __restrict__ deg,
                                                       float* __restrict__ dis, int n) {
    int i = blockIdx.x * blockDim.x + threadIdx.x;
    if (i < n) {
        int d = deg[i];
        dis[i] = (d > 0) ? rsqrtf((float)d) : 0.0f;
    }
}

// ---------------- GEMM1: X[n][j] = fp16( dis[n] * sum_k x[n][k]*W1[k][j] ) ----------------
__global__ __launch_bounds__(256) void gemm1_kernel(const float* __restrict__ A,
                                                    const float* __restrict__ W,
                                                    const float* __restrict__ dis,
                                                    __half* __restrict__ X, int n_nodes) {
    const int K = 128;
    __shared__ __align__(16) float Wt[HID][K + 4];
    __shared__ __align__(16) float xs[8][K];

    for (int i = threadIdx.x; i < K * HID; i += blockDim.x) {
        int k = i >> 5, j = i & 31;
        Wt[j][k] = W[i];
    }
    __syncthreads();

    int warp = threadIdx.x >> 5, lane = threadIdx.x & 31;
    int n = blockIdx.x * 8 + warp;
    if (n >= n_nodes) return;

    const float4* xr = (const float4*)(A + (long)n * K);
    float4* xsr = (float4*)&xs[warp][0];
    for (int i = lane; i < K / 4; i += 32) xsr[i] = xr[i];
    __syncwarp();

    const float4* wr = (const float4*)&Wt[lane][0];
    float acc = 0.0f;
#pragma unroll
    for (int k4 = 0; k4 < K / 4; k4++) {
        float4 w = wr[k4];
        float4 xx = xsr[k4];
        acc = fmaf(w.x, xx.x, acc);
        acc = fmaf(w.y, xx.y, acc);
        acc = fmaf(w.z, xx.z, acc);
        acc = fmaf(w.w, xx.w, acc);
    }
    X[n * HID + lane] = __float2half_rn(acc * dis[n]);
}

// ---------------- GEMM2 (in place): X[n][:] <- fp16( dis[n] * (h1[n][:] @ W2) ) ------------
__global__ __launch_bounds__(256) void gemm2_kernel(const float* __restrict__ W,
                                                    const float* __restrict__ dis,
                                                    __half* __restrict__ X, int n_nodes) {
    const int K = HID;
    __shared__ __align__(16) float Wt[HID][K + 4];
    __shared__ float hs[8][K];

    for (int i = threadIdx.x; i < K * HID; i += blockDim.x) {
        int k = i >> 5, j = i & 31;
        Wt[j][k] = W[i];
    }
    __syncthreads();

    int warp = threadIdx.x >> 5, lane = threadIdx.x & 31;
    int n = blockIdx.x * 8 + warp;
    if (n >= n_nodes) return;

    hs[warp][lane] = __half2float(X[n * HID + lane]);
    __syncwarp();

    float acc = 0.0f;
#pragma unroll
    for (int k = 0; k < K; k++) acc = fmaf(hs[warp][k], Wt[lane][k], acc);

    __syncwarp();
    X[n * HID + lane] = __float2half_rn(acc * dis[n]);
}

// ---------------- aggregation: edge-parallel push, dis[dst] folded in ----------------
// 32 edges per warp, 8 rounds of 4 edges. 8 lanes per edge (g = edge slot,
// q = feature quad). All loads are scalar broadcasts across the 8-lane group
// (4 distinct addrs per warp-instr -> ~1 wavefront) and front-batched as
// INDEPENDENT chains: 16 idx LDGs, then 8 dis LDGs, then 8 uint2 gathers
// (MLP 8), then 8 red.global.add.v4.f32. No shfl in the dependency path
// (round-8 lesson: shfl after LDG serializes the whole warp).
__global__ __launch_bounds__(256) void agg_push_kernel(const __half* __restrict__ X,
                                                       const int* __restrict__ row,
                                                       const int* __restrict__ col,
                                                       const float* __restrict__ dis,
                                                       float* __restrict__ Y, int e) {
    const int R = 8;
    int gw   = (blockIdx.x * blockDim.x + threadIdx.x) >> 5;
    int lane = threadIdx.x & 31;
    int g    = lane >> 3;   // edge slot within round (0..3)
    int q    = lane & 7;    // feature quad (0..7)
    int base = gw * (4 * R);
    if (base >= e) return;

    int src[R], dst[R];
#pragma unroll
    for (int r = 0; r < R; r++) {
        int eb = base + r * 4 + g;
        bool ok = eb < e;                 // e % 32 == 0 -> always true in practice
        src[r] = ok ? __ldg(&row[eb]) : 0;
        dst[r] = ok ? __ldg(&col[eb]) : -1;
    }

    float dd[R];
#pragma unroll
    for (int r = 0; r < R; r++)
        dd[r] = __ldg(&dis[dst[r] < 0 ? 0 : dst[r]]);

    uint2 v[R];
#pragma unroll
    for (int r = 0; r < R; r++)
        v[r] = __ldg((const uint2*)(X + src[r] * HID) + q);

#pragma unroll
    for (int r = 0; r < R; r++) {
        if (dst[r] >= 0) {
            __half2 h0 = *(__half2*)&v[r].x;
            __half2 h1 = *(__half2*)&v[r].y;
            float2 f0 = __half22float2(h0);
            float2 f1 = __half22float2(h1);
            float* yp = Y + dst[r] * HID + q * 4;
            asm volatile("red.global.add.v4.f32 [%0], {%1, %2, %3, %4};"
                         :: "l"(yp), "f"(f0.x * dd[r]), "f"(f0.y * dd[r]),
                            "f"(f1.x * dd[r]), "f"(f1.y * dd[r])
                         : "memory");
        }
    }
}

// ---------------- act1 (vectorized): h1 = tanh(Y + b1) -> X; Y re-zeroed ------------
// Y already carries dis[dst] scaling from the push.
__global__ __launch_bounds__(256) void act1_kernel(float* __restrict__ Y,
                                                   const float* __restrict__ b,
                                                   __half* __restrict__ X, int n_nodes) {
    int idx4 = blockIdx.x * blockDim.x + threadIdx.x;      // one float4 per thread
    int total4 = n_nodes * (HID / 4);
    if (idx4 >= total4) return;
    int j4 = (idx4 & 7) * 4;

    float4 y = ((const float4*)Y)[idx4];
    float v0 = tanhf(y.x + __ldg(&b[j4 + 0]));
    float v1 = tanhf(y.y + __ldg(&b[j4 + 1]));
    float v2 = tanhf(y.z + __ldg(&b[j4 + 2]));
    float v3 = tanhf(y.w + __ldg(&b[j4 + 3]));

    __half2 o0 = __floats2half2_rn(v0, v1);
    __half2 o1 = __floats2half2_rn(v2, v3);
    uint2 pack;
    pack.x = *(unsigned*)&o0;
    pack.y = *(unsigned*)&o1;
    ((uint2*)X)[idx4] = pack;
    ((float4*)Y)[idx4] = make_float4(0.f, 0.f, 0.f, 0.f);
}

// ---------------- fused act2 + classifier ----------------
// h2 = tanh(Y + b2) in place (Y IS the h output; dis already folded into Y),
// then logits = h2 @ Wc + bc and log_softmax. Reads NOTHING from [0,8MB).
__global__ __launch_bounds__(256) void cls_fused_kernel(float* __restrict__ Y,
                                                        const float* __restrict__ b2,
                                                        const float* __restrict__ Wc,
                                                        const float* __restrict__ bc,
                                                        float* __restrict__ out, int n_nodes) {
    const int OUT = 20;
    __shared__ float Wcs[HID * OUT];
    __shared__ float hs[8][HID];

    for (int i = threadIdx.x; i < HID * OUT; i += blockDim.x) Wcs[i] = Wc[i];
    __syncthreads();

    int warp = threadIdx.x >> 5, lane = threadIdx.x & 31;
    int n = blockIdx.x * 8 + warp;
    if (n >= n_nodes) return;

    float h = tanhf(Y[n * HID + lane] + __ldg(&b2[lane]));
    Y[n * HID + lane] = h;                 // final h2 output
    hs[warp][lane] = h;
    __syncwarp();

    float z = -INFINITY;
    if (lane < OUT) {
        float acc = bc[lane];
#pragma unroll
        for (int k = 0; k < HID; k++)
            acc = fmaf(hs[warp][k], Wcs[k * OUT + lane], acc);
        z = acc;
    }
    float m = z;
#pragma unroll
    for (int off = 16; off; off >>= 1)
        m = fmaxf(m, __shfl_xor_sync(0xffffffff, m, off));
    float ev = (lane < OUT) ? expf(z - m) : 0.0f;
    float s = ev;
#pragma unroll
    for (int off = 16; off; off >>= 1)
        s += __shfl_xor_sync(0xffffffff, s, off);
    if (lane < OUT) out[n * OUT + lane] = z - m - logf(s);
}

// ---------------- launch ----------------
extern "C" void kernel_launch(void* const* d_in, const int* in_sizes, int n_in,
                              void* d_out, int out_size) {
    const float* x  = (const float*)d_in[0];
    const int*   ei = (const int*)d_in[1];
    const float* W1 = (const float*)d_in[2];
    const float* b1 = (const float*)d_in[3];
    const float* W2 = (const float*)d_in[4];
    const float* b2 = (const float*)d_in[5];
    const float* Wc = (const float*)d_in[6];
    const float* bc = (const float*)d_in[7];

    const int n = in_sizes[0] / 128;   // 100000
    const int e = in_sizes[1] / 2;     // 3200000
    const int* row = ei;
    const int* col = ei + e;

    float*  outp = (float*)d_out;                               // final [n,20]
    float*  Y    = outp + (long)n * 20;                         // [n,32] accumulator -> h2
    __half* X    = (__half*)d_out;                              // [n,32] fp16 staging
    float*  dis  = (float*)((char*)d_out + (long)n * HID * 2);  // n floats
    int*    deg  = (int*)((char*)dis + (long)n * 4);            // n ints

    const int TB = 256;
    int gN  = (n + TB - 1) / TB;
    int gE  = (e + TB - 1) / TB;
    int gW  = (n + 7) / 8;
    int g4  = (n * (HID / 4) + TB - 1) / TB;     // float4-elementwise grid
    int gA  = (e + 255) / 256;                   // 8 warps/block x 32 edges/warp

    cudaMemsetAsync(deg, 0, (size_t)n * 4);
    cudaMemsetAsync(Y, 0, (size_t)n * HID * 4);

    count_deg_kernel<<<gE, TB>>>(col, deg, e);
    make_dis_kernel<<<gN, TB>>>(deg, dis, n);

    // Layer 1
    gemm1_kernel<<<gW, TB>>>(x, W1, dis, X, n);
    agg_push_kernel<<<gA, TB>>>(X, row, col, dis, Y, e);
    act1_kernel<<<g4, TB>>>(Y, b1, X, n);                // h1 -> X, Y re-zeroed

    // Layer 2
    gemm2_kernel<<<gW, TB>>>(W2, dis, X, n);             // t2 -> X in place
    agg_push_kernel<<<gA, TB>>>(X, row, col, dis, Y, e);

    // Fused act2 + classifier + log_softmax (clobbers X/dis/deg — all dead)
    cls_fused_kernel<<<gW, TB>>>(Y, b2, Wc, bc, outp, n);
}

// round 10
// speedup vs baseline: 1.0034x; 1.0034x over previous
#include <cuda_runtime.h>
#include <cuda_fp16.h>
#include <math.h>

// NO __device__ globals, NO static-init CUDA calls, NO local arrays.
// Scratch carved out of d_out (N*20 + N*32 floats = 20.8 MB):
//   [0      , 6.4MB)  X   : fp16 feature staging, N*32 halves (t1 / h1 / t2, reused)
//   [6.4MB  , 6.8MB)  dis : fp32 N      (1/sqrt(deg))
//   [6.8MB  , 7.2MB)  deg : int  N
//   [8.0MB  , 20.8MB) Y   : fp32 N*32   (atomic accumulator; finally holds h2 = output)
// INVARIANT: dis/deg/X are read ONLY by kernels that run before cls_fused;
// cls_fused (which writes out[0,8MB)) reads only Y + harness inputs.
// dis[dst] scaling is folded into the aggregation pushes for this reason.

#define HID 32

// ---------------- degree ----------------
__global__ __launch_bounds__(256) void count_deg_kernel(const int* __restrict__ col,
                                                        int* __restrict__ deg, int e) {
    int i = blockIdx.x * blockDim.x + threadIdx.x;
    if (i < e) atomicAdd(&deg[col[i]], 1);
}

__global__ __launch_bounds__(256) void make_dis_kernel(const int* __restrict__ deg,
                                                       float* __restrict__ dis, int n) {
    int i = blockIdx.x * blockDim.x + threadIdx.x;
    if (i < n) {
        int d = deg[i];
        dis[i] = (d > 0) ? rsqrtf((float)d) : 0.0f;
    }
}

// ---------------- GEMM1: X[n][j] = fp16( dis[n] * sum_k x[n][k]*W1[k][j] ) ----------------
__global__ __launch_bounds__(256) void gemm1_kernel(const float* __restrict__ A,
                                                    const float* __restrict__ W,
                                                    const float* __restrict__ dis,
                                                    __half* __restrict__ X, int n_nodes) {
    const int K = 128;
    __shared__ __align__(16) float Wt[HID][K + 4];
    __shared__ __align__(16) float xs[8][K];

    for (int i = threadIdx.x; i < K * HID; i += blockDim.x) {
        int k = i >> 5, j = i & 31;
        Wt[j][k] = W[i];
    }
    __syncthreads();

    int warp = threadIdx.x >> 5, lane = threadIdx.x & 31;
    int n = blockIdx.x * 8 + warp;
    if (n >= n_nodes) return;

    const float4* xr = (const float4*)(A + (long)n * K);
    float4* xsr = (float4*)&xs[warp][0];
    for (int i = lane; i < K / 4; i += 32) xsr[i] = xr[i];
    __syncwarp();

    const float4* wr = (const float4*)&Wt[lane][0];
    float acc = 0.0f;
#pragma unroll
    for (int k4 = 0; k4 < K / 4; k4++) {
        float4 w = wr[k4];
        float4 xx = xsr[k4];
        acc = fmaf(w.x, xx.x, acc);
        acc = fmaf(w.y, xx.y, acc);
        acc = fmaf(w.z, xx.z, acc);
        acc = fmaf(w.w, xx.w, acc);
    }
    X[n * HID + lane] = __float2half_rn(acc * dis[n]);
}

// ---------------- GEMM2 (in place): X[n][:] <- fp16( dis[n] * (h1[n][:] @ W2) ) ------------
__global__ __launch_bounds__(256) void gemm2_kernel(const float* __restrict__ W,
                                                    const float* __restrict__ dis,
                                                    __half* __restrict__ X, int n_nodes) {
    const int K = HID;
    __shared__ __align__(16) float Wt[HID][K + 4];
    __shared__ float hs[8][K];

    for (int i = threadIdx.x; i < K * HID; i += blockDim.x) {
        int k = i >> 5, j = i & 31;
        Wt[j][k] = W[i];
    }
    __syncthreads();

    int warp = threadIdx.x >> 5, lane = threadIdx.x & 31;
    int n = blockIdx.x * 8 + warp;
    if (n >= n_nodes) return;

    hs[warp][lane] = __half2float(X[n * HID + lane]);
    __syncwarp();

    float acc = 0.0f;
#pragma unroll
    for (int k = 0; k < K; k++) acc = fmaf(hs[warp][k], Wt[lane][k], acc);

    __syncwarp();
    X[n * HID + lane] = __float2half_rn(acc * dis[n]);
}

// ---------------- aggregation: edge-parallel push, dis[dst] folded in ----------------
// ROUND-5 STRUCTURE (proven fastest: 28->~32 regs, occ ~86%) + dis fold.
// 16 edges per warp in 4 rounds of 4 edges. 8 lanes per edge (g = edge slot,
// q = feature quad). All loads scalar-broadcast across the 8-lane group
// (4 distinct addrs per warp-instr) and front-batched as INDEPENDENT chains:
// 8 idx LDGs, 4 dis LDGs, 4 uint2 gathers (MLP 4), then 4 REDs. No shfl
// (round-8 lesson), no R=8 (round-9 lesson: occupancy collapse).
__global__ __launch_bounds__(256) void agg_push_kernel(const __half* __restrict__ X,
                                                       const int* __restrict__ row,
                                                       const int* __restrict__ col,
                                                       const float* __restrict__ dis,
                                                       float* __restrict__ Y, int e) {
    const int R = 4;
    int gw   = (blockIdx.x * blockDim.x + threadIdx.x) >> 5;
    int lane = threadIdx.x & 31;
    int g    = lane >> 3;   // edge slot within round (0..3)
    int q    = lane & 7;    // feature quad (0..7)
    int base = gw * (4 * R);
    if (base >= e) return;

    int src[R], dst[R];
#pragma unroll
    for (int r = 0; r < R; r++) {
        int eb = base + r * 4 + g;
        bool ok = eb < e;                 // e % 16 == 0 -> always true in practice
        src[r] = ok ? __ldg(&row[eb]) : 0;
        dst[r] = ok ? __ldg(&col[eb]) : -1;
    }

    float dd[R];
#pragma unroll
    for (int r = 0; r < R; r++)
        dd[r] = __ldg(&dis[dst[r] < 0 ? 0 : dst[r]]);

    uint2 v[R];
#pragma unroll
    for (int r = 0; r < R; r++)
        v[r] = __ldg((const uint2*)(X + src[r] * HID) + q);

#pragma unroll
    for (int r = 0; r < R; r++) {
        if (dst[r] >= 0) {
            __half2 h0 = *(__half2*)&v[r].x;
            __half2 h1 = *(__half2*)&v[r].y;
            float2 f0 = __half22float2(h0);
            float2 f1 = __half22float2(h1);
            float* yp = Y + dst[r] * HID + q * 4;
            asm volatile("red.global.add.v4.f32 [%0], {%1, %2, %3, %4};"
                         :: "l"(yp), "f"(f0.x * dd[r]), "f"(f0.y * dd[r]),
                            "f"(f1.x * dd[r]), "f"(f1.y * dd[r])
                         : "memory");
        }
    }
}

// ---------------- act1 (vectorized): h1 = tanh(Y + b1) -> X; Y re-zeroed ------------
// Y already carries dis[dst] scaling from the push.
__global__ __launch_bounds__(256) void act1_kernel(float* __restrict__ Y,
                                                   const float* __restrict__ b,
                                                   __half* __restrict__ X, int n_nodes) {
    int idx4 = blockIdx.x * blockDim.x + threadIdx.x;      // one float4 per thread
    int total4 = n_nodes * (HID / 4);
    if (idx4 >= total4) return;
    int j4 = (idx4 & 7) * 4;

    float4 y = ((const float4*)Y)[idx4];
    float v0 = tanhf(y.x + __ldg(&b[j4 + 0]));
    float v1 = tanhf(y.y + __ldg(&b[j4 + 1]));
    float v2 = tanhf(y.z + __ldg(&b[j4 + 2]));
    float v3 = tanhf(y.w + __ldg(&b[j4 + 3]));

    __half2 o0 = __floats2half2_rn(v0, v1);
    __half2 o1 = __floats2half2_rn(v2, v3);
    uint2 pack;
    pack.x = *(unsigned*)&o0;
    pack.y = *(unsigned*)&o1;
    ((uint2*)X)[idx4] = pack;
    ((float4*)Y)[idx4] = make_float4(0.f, 0.f, 0.f, 0.f);
}

// ---------------- fused act2 + classifier ----------------
// h2 = tanh(Y + b2) in place (Y IS the h output; dis already folded into Y),
// then logits = h2 @ Wc + bc and log_softmax. Reads NOTHING from [0,8MB).
__global__ __launch_bounds__(256) void cls_fused_kernel(float* __restrict__ Y,
                                                        const float* __restrict__ b2,
                                                        const float* __restrict__ Wc,
                                                        const float* __restrict__ bc,
                                                        float* __restrict__ out, int n_nodes) {
    const int OUT = 20;
    __shared__ float Wcs[HID * OUT];
    __shared__ float hs[8][HID];

    for (int i = threadIdx.x; i < HID * OUT; i += blockDim.x) Wcs[i] = Wc[i];
    __syncthreads();

    int warp = threadIdx.x >> 5, lane = threadIdx.x & 31;
    int n = blockIdx.x * 8 + warp;
    if (n >= n_nodes) return;

    float h = tanhf(Y[n * HID + lane] + __ldg(&b2[lane]));
    Y[n * HID + lane] = h;                 // final h2 output
    hs[warp][lane] = h;
    __syncwarp();

    float z = -INFINITY;
    if (lane < OUT) {
        float acc = bc[lane];
#pragma unroll
        for (int k = 0; k < HID; k++)
            acc = fmaf(hs[warp][k], Wcs[k * OUT + lane], acc);
        z = acc;
    }
    float m = z;
#pragma unroll
    for (int off = 16; off; off >>= 1)
        m = fmaxf(m, __shfl_xor_sync(0xffffffff, m, off));
    float ev = (lane < OUT) ? expf(z - m) : 0.0f;
    float s = ev;
#pragma unroll
    for (int off = 16; off; off >>= 1)
        s += __shfl_xor_sync(0xffffffff, s, off);
    if (lane < OUT) out[n * OUT + lane] = z - m - logf(s);
}

// ---------------- launch ----------------
extern "C" void kernel_launch(void* const* d_in, const int* in_sizes, int n_in,
                              void* d_out, int out_size) {
    const float* x  = (const float*)d_in[0];
    const int*   ei = (const int*)d_in[1];
    const float* W1 = (const float*)d_in[2];
    const float* b1 = (const float*)d_in[3];
    const float* W2 = (const float*)d_in[4];
    const float* b2 = (const float*)d_in[5];
    const float* Wc = (const float*)d_in[6];
    const float* bc = (const float*)d_in[7];

    const int n = in_sizes[0] / 128;   // 100000
    const int e = in_sizes[1] / 2;     // 3200000
    const int* row = ei;
    const int* col = ei + e;

    float*  outp = (float*)d_out;                               // final [n,20]
    float*  Y    = outp + (long)n * 20;                         // [n,32] accumulator -> h2
    __half* X    = (__half*)d_out;                              // [n,32] fp16 staging
    float*  dis  = (float*)((char*)d_out + (long)n * HID * 2);  // n floats
    int*    deg  = (int*)((char*)dis + (long)n * 4);            // n ints

    const int TB = 256;
    int gN  = (n + TB - 1) / TB;
    int gE  = (e + TB - 1) / TB;
    int gW  = (n + 7) / 8;
    int g4  = (n * (HID / 4) + TB - 1) / TB;     // float4-elementwise grid
    int gA  = (e + 127) / 128;                   // 8 warps/block x 16 edges/warp

    cudaMemsetAsync(deg, 0, (size_t)n * 4);
    cudaMemsetAsync(Y, 0, (size_t)n * HID * 4);

    count_deg_kernel<<<gE, TB>>>(col, deg, e);
    make_dis_kernel<<<gN, TB>>>(deg, dis, n);

    // Layer 1
    gemm1_kernel<<<gW, TB>>>(x, W1, dis, X, n);
    agg_push_kernel<<<gA, TB>>>(X, row, col, dis, Y, e);
    act1_kernel<<<g4, TB>>>(Y, b1, X, n);                // h1 -> X, Y re-zeroed

    // Layer 2
    gemm2_kernel<<<gW, TB>>>(W2, dis, X, n);             // t2 -> X in place
    agg_push_kernel<<<gA, TB>>>(X, row, col, dis, Y, e);

    // Fused act2 + classifier + log_softmax (clobbers X/dis/deg — all dead)
    cls_fused_kernel<<<gW, TB>>>(Y, b2, Wc, bc, outp, n);
}

// round 14
// speedup vs baseline: 1.0574x; 1.0538x over previous
#include <cuda_runtime.h>
#include <cuda_fp16.h>
#include <math.h>

// NO __device__ globals, NO static-init CUDA calls, NO local arrays.
// Scratch carved out of d_out (N*20 + N*32 floats = 20.8 MB):
//   [0      , 6.4MB)  X   : fp16 feature staging, N*32 halves (t1 / h1 / t2, reused)
//   [6.4MB  , 6.8MB)  dis : fp32 N      (1/sqrt(deg))
//   [6.8MB  , 7.2MB)  deg : int  N
//   [8.0MB  , 20.8MB) Y   : fp32 N*32   (atomic accumulator; finally holds h2 = output)
// RACE RULE: the out region [0,8MB) (which holds X/dis/deg scratch) is only
// written by cls_kernel, and cls_kernel reads NOTHING from it (only Y + inputs).
// All kernels that read dis run before cls and write only X/Y.

#define HID 32

// ---------------- degree ----------------
__global__ __launch_bounds__(256) void count_deg_kernel(const int* __restrict__ col,
                                                        int* __restrict__ deg, int e) {
    int i = blockIdx.x * blockDim.x + threadIdx.x;
    if (i < e) atomicAdd(&deg[col[i]], 1);
}

__global__ __launch_bounds__(256) void make_dis_kernel(const int* __restrict__ deg,
                                                       float* __restrict__ dis, int n) {
    int i = blockIdx.x * blockDim.x + threadIdx.x;
    if (i < n) {
        int d = deg[i];
        dis[i] = (d > 0) ? rsqrtf((float)d) : 0.0f;
    }
}

// ---------------- GEMM1: X[n][j] = fp16( dis[n] * sum_k x[n][k]*W1[k][j] ) ----------------
__global__ __launch_bounds__(256) void gemm1_kernel(const float* __restrict__ A,
                                                    const float* __restrict__ W,
                                                    const float* __restrict__ dis,
                                                    __half* __restrict__ X, int n_nodes) {
    const int K = 128;
    __shared__ __align__(16) float Wt[HID][K + 4];
    __shared__ __align__(16) float xs[8][K];

    for (int i = threadIdx.x; i < K * HID; i += blockDim.x) {
        int k = i >> 5, j = i & 31;
        Wt[j][k] = W[i];
    }
    __syncthreads();

    int warp = threadIdx.x >> 5, lane = threadIdx.x & 31;
    int n = blockIdx.x * 8 + warp;
    if (n >= n_nodes) return;

    const float4* xr = (const float4*)(A + (long)n * K);
    float4* xsr = (float4*)&xs[warp][0];
    for (int i = lane; i < K / 4; i += 32) xsr[i] = xr[i];
    __syncwarp();

    const float4* wr = (const float4*)&Wt[lane][0];
    float acc = 0.0f;
#pragma unroll
    for (int k4 = 0; k4 < K / 4; k4++) {
        float4 w = wr[k4];
        float4 xx = xsr[k4];
        acc = fmaf(w.x, xx.x, acc);
        acc = fmaf(w.y, xx.y, acc);
        acc = fmaf(w.z, xx.z, acc);
        acc = fmaf(w.w, xx.w, acc);
    }
    X[n * HID + lane] = __float2half_rn(acc * dis[n]);
}

// ---------------- GEMM2 (in place): X[n][:] <- fp16( dis[n] * (h1[n][:] @ W2) ) ------------
__global__ __launch_bounds__(256) void gemm2_kernel(const float* __restrict__ W,
                                                    const float* __restrict__ dis,
                                                    __half* __restrict__ X, int n_nodes) {
    const int K = HID;
    __shared__ __align__(16) float Wt[HID][K + 4];
    __shared__ float hs[8][K];

    for (int i = threadIdx.x; i < K * HID; i += blockDim.x) {
        int k = i >> 5, j = i & 31;
        Wt[j][k] = W[i];
    }
    __syncthreads();

    int warp = threadIdx.x >> 5, lane = threadIdx.x & 31;
    int n = blockIdx.x * 8 + warp;
    if (n >= n_nodes) return;

    hs[warp][lane] = __half2float(X[n * HID + lane]);
    __syncwarp();

    float acc = 0.0f;
#pragma unroll
    for (int k = 0; k < K; k++) acc = fmaf(hs[warp][k], Wt[lane][k], acc);

    __syncwarp();
    X[n * HID + lane] = __float2half_rn(acc * dis[n]);
}

// ---------------- aggregation: edge-parallel push (CLEAN: no dis) ----------------
// 16 edges per warp. Each 8-lane group g owns 4 CONSECUTIVE edges
// [base+4g, base+4g+4), so ONE broadcast int4 load yields the group's 4 src
// indices (1 wavefront per warp-instr: 4 distinct 16B in one 64B span), same
// for dst. Then 4 independent uint2 gathers (MLP 4) and 4 red.v4.f32 pushes.
// Wavefronts per 16 edges: 2 idx + 16 gather + 16 red (was 8 idx in R5).
// No dis here (round-10 lesson: +any instrs at L1=89% costs linearly),
// no shfl (round-8), R=4 / ~28 regs (round-9: occupancy > batching).
__global__ __launch_bounds__(256) void agg_push_kernel(const __half* __restrict__ X,
                                                       const int* __restrict__ row,
                                                       const int* __restrict__ col,
                                                       float* __restrict__ Y, int e) {
    int gw   = (blockIdx.x * blockDim.x + threadIdx.x) >> 5;
    int lane = threadIdx.x & 31;
    int g    = lane >> 3;   // 8-lane group (0..3)
    int q    = lane & 7;    // feature quad (0..7)
    int base = gw * 16;
    if (base >= e) return;

    int4 sv, dv;
    if (base + 16 <= e) {   // e % 16 == 0 -> always this path
        sv = __ldg((const int4*)(row + base) + g);
        dv = __ldg((const int4*)(col + base) + g);
    } else {
        int eb = base + g * 4;
        sv.x = (eb + 0 < e) ? __ldg(&row[eb + 0]) : 0;
        sv.y = (eb + 1 < e) ? __ldg(&row[eb + 1]) : 0;
        sv.z = (eb + 2 < e) ? __ldg(&row[eb + 2]) : 0;
        sv.w = (eb + 3 < e) ? __ldg(&row[eb + 3]) : 0;
        dv.x = (eb + 0 < e) ? __ldg(&col[eb + 0]) : -1;
        dv.y = (eb + 1 < e) ? __ldg(&col[eb + 1]) : -1;
        dv.z = (eb + 2 < e) ? __ldg(&col[eb + 2]) : -1;
        dv.w = (eb + 3 < e) ? __ldg(&col[eb + 3]) : -1;
    }

    uint2 v0 = __ldg((const uint2*)(X + sv.x * HID) + q);
    uint2 v1 = __ldg((const uint2*)(X + sv.y * HID) + q);
    uint2 v2 = __ldg((const uint2*)(X + sv.z * HID) + q);
    uint2 v3 = __ldg((const uint2*)(X + sv.w * HID) + q);

#define PUSH(vv, dd)                                                          \
    if ((dd) >= 0) {                                                          \
        __half2 h0 = *(__half2*)&(vv).x;                                      \
        __half2 h1 = *(__half2*)&(vv).y;                                      \
        float2 f0 = __half22float2(h0);                                       \
        float2 f1 = __half22float2(h1);                                       \
        float* yp = Y + (dd) * HID + q * 4;                                   \
        asm volatile("red.global.add.v4.f32 [%0], {%1, %2, %3, %4};"          \
                     :: "l"(yp), "f"(f0.x), "f"(f0.y), "f"(f1.x), "f"(f1.y)   \
                     : "memory");                                             \
    }
    PUSH(v0, dv.x)
    PUSH(v1, dv.y)
    PUSH(v2, dv.z)
    PUSH(v3, dv.w)
#undef PUSH
}

// ---------------- act1 (float4): h1 = tanh(dis*Y + b1) -> X; Y re-zeroed ------------
__global__ __launch_bounds__(256) void act1_kernel(float* __restrict__ Y,
                                                   const float* __restrict__ dis,
                                                   const float* __restrict__ b,
                                                   __half* __restrict__ X, int n_nodes) {
    int idx4 = blockIdx.x * blockDim.x + threadIdx.x;
    int total4 = n_nodes * (HID / 4);
    if (idx4 >= total4) return;
    int node = idx4 >> 3;
    int j4 = (idx4 & 7) * 4;
    float dn = __ldg(&dis[node]);

    float4 y = ((const float4*)Y)[idx4];
    float v0 = tanhf(fmaf(dn, y.x, __ldg(&b[j4 + 0])));
    float v1 = tanhf(fmaf(dn, y.y, __ldg(&b[j4 + 1])));
    float v2 = tanhf(fmaf(dn, y.z, __ldg(&b[j4 + 2])));
    float v3 = tanhf(fmaf(dn, y.w, __ldg(&b[j4 + 3])));

    __half2 o0 = __floats2half2_rn(v0, v1);
    __half2 o1 = __floats2half2_rn(v2, v3);
    uint2 pack;
    pack.x = *(unsigned*)&o0;
    pack.y = *(unsigned*)&o1;
    ((uint2*)X)[idx4] = pack;
    ((float4*)Y)[idx4] = make_float4(0.f, 0.f, 0.f, 0.f);
}

// ---------------- act2 (float4): h2 = tanh(dis*Y + b2) -> Y in place ------------
// Reads dis (out-region scratch) but writes ONLY Y -> race-safe.
__global__ __launch_bounds__(256) void act2_kernel(float* __restrict__ Y,
                                                   const float* __restrict__ dis,
                                                   const float* __restrict__ b, int n_nodes) {
    int idx4 = blockIdx.x * blockDim.x + threadIdx.x;
    int total4 = n_nodes * (HID / 4);
    if (idx4 >= total4) return;
    int node = idx4 >> 3;
    int j4 = (idx4 & 7) * 4;
    float dn = __ldg(&dis[node]);

    float4 y = ((const float4*)Y)[idx4];
    y.x = tanhf(fmaf(dn, y.x, __ldg(&b[j4 + 0])));
    y.y = tanhf(fmaf(dn, y.y, __ldg(&b[j4 + 1])));
    y.z = tanhf(fmaf(dn, y.z, __ldg(&b[j4 + 2])));
    y.w = tanhf(fmaf(dn, y.w, __ldg(&b[j4 + 3])));
    ((float4*)Y)[idx4] = y;
}

// ---------------- classifier: logits + log_softmax ----------------
// Reads ONLY Y (finished h2) + harness inputs; writes out[0,8MB). Race-safe.
__global__ __launch_bounds__(256) void cls_kernel(const float* __restrict__ h,
                                                  const float* __restrict__ Wc,
                                                  const float* __restrict__ bc,
                                                  float* __restrict__ out, int n_nodes) {
    const int OUT = 20;
    __shared__ float Wcs[HID * OUT];
    __shared__ float hs[8][HID];

    for (int i = threadIdx.x; i < HID * OUT; i += blockDim.x) Wcs[i] = Wc[i];
    __syncthreads();

    int warp = threadIdx.x >> 5, lane = threadIdx.x & 31;
    int n = blockIdx.x * 8 + warp;
    if (n >= n_nodes) return;

    hs[warp][lane] = h[n * HID + lane];
    __syncwarp();

    float z = -INFINITY;
    if (lane < OUT) {
        float acc = bc[lane];
#pragma unroll
        for (int k = 0; k < HID; k++)
            acc = fmaf(hs[warp][k], Wcs[k * OUT + lane], acc);
        z = acc;
    }
    float m = z;
#pragma unroll
    for (int off = 16; off; off >>= 1)
        m = fmaxf(m, __shfl_xor_sync(0xffffffff, m, off));
    float ev = (lane < OUT) ? expf(z - m) : 0.0f;
    float s = ev;
#pragma unroll
    for (int off = 16; off; off >>= 1)
        s += __shfl_xor_sync(0xffffffff, s, off);
    if (lane < OUT) out[n * OUT + lane] = z - m - logf(s);
}

// ---------------- launch ----------------
extern "C" void kernel_launch(void* const* d_in, const int* in_sizes, int n_in,
                              void* d_out, int out_size) {
    const float* x  = (const float*)d_in[0];
    const int*   ei = (const int*)d_in[1];
    const float* W1 = (const float*)d_in[2];
    const float* b1 = (const float*)d_in[3];
    const float* W2 = (const float*)d_in[4];
    const float* b2 = (const float*)d_in[5];
    const float* Wc = (const float*)d_in[6];
    const float* bc = (const float*)d_in[7];

    const int n = in_sizes[0] / 128;   // 100000
    const int e = in_sizes[1] / 2;     // 3200000
    const int* row = ei;
    const int* col = ei + e;

    float*  outp = (float*)d_out;                               // final [n,20]
    float*  Y    = outp + (long)n * 20;                         // [n,32] accumulator -> h2
    __half* X    = (__half*)d_out;                              // [n,32] fp16 staging
    float*  dis  = (float*)((char*)d_out + (long)n * HID * 2);  // n floats
    int*    deg  = (int*)((char*)dis + (long)n * 4);            // n ints

    const int TB = 256;
    int gN  = (n + TB - 1) / TB;
    int gE  = (e + TB - 1) / TB;
    int gW  = (n + 7) / 8;
    int g4  = (n * (HID / 4) + TB - 1) / TB;     // float4-elementwise grid
    int gA  = (e + 127) / 128;                   // 8 warps/block x 16 edges/warp

    cudaMemsetAsync(deg, 0, (size_t)n * 4);
    cudaMemsetAsync(Y, 0, (size_t)n * HID * 4);

    count_deg_kernel<<<gE, TB>>>(col, deg, e);
    make_dis_kernel<<<gN, TB>>>(deg, dis, n);

    // Layer 1
    gemm1_kernel<<<gW, TB>>>(x, W1, dis, X, n);
    agg_push_kernel<<<gA, TB>>>(X, row, col, Y, e);
    act1_kernel<<<g4, TB>>>(Y, dis, b1, X, n);           // h1 -> X, Y re-zeroed

    // Layer 2
    gemm2_kernel<<<gW, TB>>>(W2, dis, X, n);             // t2 -> X in place
    agg_push_kernel<<<gA, TB>>>(X, row, col, Y, e);
    act2_kernel<<<g4, TB>>>(Y, dis, b2, n);              // h2 -> Y (= output h region)

    // Classifier + log_softmax (reads only Y; clobbers X/dis/deg — all dead)
    cls_kernel<<<gW, TB>>>(Y, Wc, bc, outp, n);
}